// round 3
// baseline (speedup 1.0000x reference)
#include <cuda_runtime.h>
#include <cuda_bf16.h>
#include <cstdint>

// Problem dims
#define BB 16384
#define FF 128
#define HH 1024
#define NSTEPS 8

#define K1 (3 * FF)    // 384  : split-K for layer 1
#define K2 (3 * HH)    // 3072 : split-K for layers 2/3

// ---------------- scratch (static __device__, no allocation) ----------------
// Weights, split layout [Bh ; Bh ; Bl] along K
__device__ __align__(16) __nv_bfloat16 g_W1x[K1 * HH];
__device__ __align__(16) __nv_bfloat16 g_W2x[K2 * HH];
__device__ __align__(16) __nv_bfloat16 g_W3x[K2 * FF];
// Activations, split layout [Ah | Al | Ah] along K
__device__ __align__(16) __nv_bfloat16 g_epsx[BB * K1];   // [eps | 0 | eps]
__device__ __align__(16) __nv_bfloat16 g_XSx [BB * K1];
__device__ __align__(16) __nv_bfloat16 g_H1px[(size_t)BB * K2];
__device__ __align__(16) __nv_bfloat16 g_H1tx[(size_t)BB * K2];
__device__ __align__(16) __nv_bfloat16 g_H2px[(size_t)BB * K2];
__device__ __align__(16) __nv_bfloat16 g_H2tx[(size_t)BB * K2];
// fp32 state
__device__ float g_T1 [(size_t)BB * HH];   // eps @ W1 (const tangent pre-act, exact-ish)
__device__ float g_D2f[(size_t)BB * HH];   // 1 - h2^2
__device__ float g_K   [BB * FF];
__device__ float g_trace[BB];
__device__ float g_xcur[BB * FF];
__device__ float g_accX[BB * FF];
__device__ float g_accL[BB];
__device__ float g_logdet[BB];

// ---------------- helpers ----------------
__device__ __forceinline__ uint32_t smem_u32(const void* p) {
    return (uint32_t)__cvta_generic_to_shared(p);
}
__device__ __forceinline__ void cp16(uint32_t s, const void* g) {
    asm volatile("cp.async.cg.shared.global [%0], [%1], 16;\n" :: "r"(s), "l"(g));
}
__device__ __forceinline__ void cp_commit() { asm volatile("cp.async.commit_group;\n"); }
__device__ __forceinline__ void cp_wait0()  { asm volatile("cp.async.wait_group 0;\n"); }

__device__ __forceinline__ void ldsm4(uint32_t* r, uint32_t a) {
    asm volatile("ldmatrix.sync.aligned.m8n8.x4.shared.b16 {%0,%1,%2,%3},[%4];"
                 : "=r"(r[0]), "=r"(r[1]), "=r"(r[2]), "=r"(r[3]) : "r"(a));
}
__device__ __forceinline__ void ldsm4t(uint32_t* r, uint32_t a) {
    asm volatile("ldmatrix.sync.aligned.m8n8.x4.trans.shared.b16 {%0,%1,%2,%3},[%4];"
                 : "=r"(r[0]), "=r"(r[1]), "=r"(r[2]), "=r"(r[3]) : "r"(a));
}
__device__ __forceinline__ void mma16816(float* c, const uint32_t* a, uint32_t b0, uint32_t b1) {
    asm volatile(
        "mma.sync.aligned.m16n8k16.row.col.f32.bf16.bf16.f32 "
        "{%0,%1,%2,%3},{%4,%5,%6,%7},{%8,%9},{%0,%1,%2,%3};"
        : "+f"(c[0]), "+f"(c[1]), "+f"(c[2]), "+f"(c[3])
        : "r"(a[0]), "r"(a[1]), "r"(a[2]), "r"(a[3]), "r"(b0), "r"(b1));
}
__device__ __forceinline__ void split2(float v, __nv_bfloat16& h, __nv_bfloat16& l) {
    h = __float2bfloat16(v);
    l = __float2bfloat16(v - __bfloat162float(h));
}

// ---------------- epilogue ids ----------------
enum { E_T1 = 0, E_L1, E_L2P, E_L2T, E_L3P, E_L3T };

// ---------------- fused GEMM: C = A @ B with per-layer epilogue ----------------
constexpr int BM = 128, BN = 128, BK = 32;

template <int EPI>
__global__ __launch_bounds__(256)
void gemm_k(const float* __restrict__ bias, const float* __restrict__ w1t,
            float tval, const float* __restrict__ epsf) {
    constexpr int Nd = (EPI == E_L3P || EPI == E_L3T) ? FF : HH;
    constexpr int Kd = (EPI == E_T1 || EPI == E_L1) ? K1 : K2;

    const __nv_bfloat16* Ag =
        (EPI == E_T1)  ? g_epsx :
        (EPI == E_L1)  ? g_XSx  :
        (EPI == E_L2P) ? g_H1px :
        (EPI == E_L2T) ? g_H1tx :
        (EPI == E_L3P) ? g_H2px : g_H2tx;
    const __nv_bfloat16* Bg =
        (EPI == E_T1 || EPI == E_L1) ? g_W1x :
        (EPI == E_L2P || EPI == E_L2T) ? g_W2x : g_W3x;

    __shared__ __align__(16) __nv_bfloat16 As[2][BM][BK + 8];
    __shared__ __align__(16) __nv_bfloat16 Bs[2][BK][BN + 8];
    __shared__ float rsum[BM];

    const int tid = threadIdx.x, lane = tid & 31, warp = tid >> 5;
    const int m0 = blockIdx.y * BM, n0 = blockIdx.x * BN;
    const int wm = (warp & 1) * 64, wn = (warp >> 1) * 32;

    if (EPI == E_L3T && tid < BM) rsum[tid] = 0.f;

    float c[4][4][4];
#pragma unroll
    for (int i = 0; i < 4; i++)
#pragma unroll
        for (int j = 0; j < 4; j++)
#pragma unroll
            for (int k = 0; k < 4; k++) c[i][j][k] = 0.f;

    auto prefetch = [&](int kt, int bufi) {
        int k0 = kt * BK;
#pragma unroll
        for (int i = 0; i < 2; i++) {   // A: 512 chunks of 8 bf16
            int ch = tid * 2 + i;
            int r = ch >> 2, c8 = (ch & 3) * 8;
            cp16(smem_u32(&As[bufi][r][c8]), Ag + (size_t)(m0 + r) * Kd + k0 + c8);
        }
#pragma unroll
        for (int i = 0; i < 2; i++) {   // B: 512 chunks
            int ch = tid * 2 + i;
            int r = ch >> 4, c8 = (ch & 15) * 8;
            cp16(smem_u32(&Bs[bufi][r][c8]), Bg + (size_t)(k0 + r) * Nd + n0 + c8);
        }
        cp_commit();
    };

    const int nk = Kd / BK;
    prefetch(0, 0);
    int buf = 0;
    for (int kt = 0; kt < nk; kt++) {
        cp_wait0();
        __syncthreads();
        if (kt + 1 < nk) prefetch(kt + 1, buf ^ 1);
#pragma unroll
        for (int kk = 0; kk < BK; kk += 16) {
            uint32_t a[4][4];
#pragma unroll
            for (int mf = 0; mf < 4; mf++)
                ldsm4(a[mf], smem_u32(&As[buf][wm + mf * 16 + (lane & 15)]
                                          [kk + ((lane >> 4) << 3)]));
            uint32_t bq[2][4];
#pragma unroll
            for (int nb = 0; nb < 2; nb++)
                ldsm4t(bq[nb], smem_u32(&Bs[buf][kk + (lane & 7) + ((lane >> 3) & 1) * 8]
                                            [wn + nb * 16 + ((lane >> 4) << 3)]));
#pragma unroll
            for (int mf = 0; mf < 4; mf++)
#pragma unroll
                for (int ns = 0; ns < 4; ns++)
                    mma16816(c[mf][ns], a[mf], bq[ns >> 1][(ns & 1) * 2],
                             bq[ns >> 1][(ns & 1) * 2 + 1]);
        }
        buf ^= 1;
        __syncthreads();
    }

    // ---------------- epilogues ----------------
    const int g = lane >> 2, tig = lane & 3;

    if (EPI == E_L3T) {
#pragma unroll
        for (int mf = 0; mf < 4; mf++) {
            int r0 = m0 + wm + mf * 16 + g;
            float s0 = 0.f, s1 = 0.f;
#pragma unroll
            for (int ns = 0; ns < 4; ns++) {
                int col = n0 + wn + ns * 8 + tig * 2;
                s0 += c[mf][ns][0] * epsf[r0 * FF + col] +
                      c[mf][ns][1] * epsf[r0 * FF + col + 1];
                s1 += c[mf][ns][2] * epsf[(r0 + 8) * FF + col] +
                      c[mf][ns][3] * epsf[(r0 + 8) * FF + col + 1];
            }
            s0 += __shfl_xor_sync(0xffffffffu, s0, 1);
            s0 += __shfl_xor_sync(0xffffffffu, s0, 2);
            s1 += __shfl_xor_sync(0xffffffffu, s1, 1);
            s1 += __shfl_xor_sync(0xffffffffu, s1, 2);
            if (tig == 0) {
                atomicAdd(&rsum[wm + mf * 16 + g], s0);
                atomicAdd(&rsum[wm + mf * 16 + g + 8], s1);
            }
        }
        __syncthreads();
        if (tid < BM) g_trace[m0 + tid] = rsum[tid];
        return;
    }

#pragma unroll
    for (int mf = 0; mf < 4; mf++) {
#pragma unroll
        for (int ns = 0; ns < 4; ns++) {
            int col = n0 + wn + ns * 8 + tig * 2;
            int r0 = m0 + wm + mf * 16 + g;
#pragma unroll
            for (int half = 0; half < 2; half++) {
                int r = r0 + half * 8;
                float v0 = c[mf][ns][half * 2 + 0];
                float v1 = c[mf][ns][half * 2 + 1];
                if (EPI == E_T1) {
                    size_t idx = (size_t)r * HH + col;
                    g_T1[idx] = v0; g_T1[idx + 1] = v1;
                } else if (EPI == E_L1) {
                    size_t tix = (size_t)r * HH + col;
                    size_t ob  = (size_t)r * K2 + col;       // hidden split buffers
                    float h0 = tanhf(v0 + tval * w1t[col] + bias[col]);
                    float h1 = tanhf(v1 + tval * w1t[col + 1] + bias[col + 1]);
                    __nv_bfloat16 hh, hl;
                    split2(h0, hh, hl);
                    g_H1px[ob] = hh; g_H1px[ob + HH] = hl; g_H1px[ob + 2 * HH] = hh;
                    split2(h1, hh, hl);
                    g_H1px[ob + 1] = hh; g_H1px[ob + HH + 1] = hl; g_H1px[ob + 2 * HH + 1] = hh;
                    float u0 = (1.f - h0 * h0) * g_T1[tix];
                    float u1 = (1.f - h1 * h1) * g_T1[tix + 1];
                    split2(u0, hh, hl);
                    g_H1tx[ob] = hh; g_H1tx[ob + HH] = hl; g_H1tx[ob + 2 * HH] = hh;
                    split2(u1, hh, hl);
                    g_H1tx[ob + 1] = hh; g_H1tx[ob + HH + 1] = hl; g_H1tx[ob + 2 * HH + 1] = hh;
                } else if (EPI == E_L2P) {
                    size_t dix = (size_t)r * HH + col;
                    size_t ob  = (size_t)r * K2 + col;
                    float h0 = tanhf(v0 + bias[col]);
                    float h1 = tanhf(v1 + bias[col + 1]);
                    __nv_bfloat16 hh, hl;
                    split2(h0, hh, hl);
                    g_H2px[ob] = hh; g_H2px[ob + HH] = hl; g_H2px[ob + 2 * HH] = hh;
                    split2(h1, hh, hl);
                    g_H2px[ob + 1] = hh; g_H2px[ob + HH + 1] = hl; g_H2px[ob + 2 * HH + 1] = hh;
                    g_D2f[dix]     = 1.f - h0 * h0;
                    g_D2f[dix + 1] = 1.f - h1 * h1;
                } else if (EPI == E_L2T) {
                    size_t dix = (size_t)r * HH + col;
                    size_t ob  = (size_t)r * K2 + col;
                    float u0 = v0 * g_D2f[dix];
                    float u1 = v1 * g_D2f[dix + 1];
                    __nv_bfloat16 hh, hl;
                    split2(u0, hh, hl);
                    g_H2tx[ob] = hh; g_H2tx[ob + HH] = hl; g_H2tx[ob + 2 * HH] = hh;
                    split2(u1, hh, hl);
                    g_H2tx[ob + 1] = hh; g_H2tx[ob + HH + 1] = hl; g_H2tx[ob + 2 * HH + 1] = hh;
                } else if (EPI == E_L3P) {
                    int idx = r * FF + col;
                    g_K[idx]     = v0 + bias[col];
                    g_K[idx + 1] = v1 + bias[col + 1];
                }
            }
        }
    }
}

// ---------------- setup / RK4 bookkeeping / output ----------------
__global__ void setup_k(const float* __restrict__ x, const float* __restrict__ eps,
                        const float* __restrict__ W1, const float* __restrict__ W2,
                        const float* __restrict__ W3) {
    int i = blockIdx.x * blockDim.x + threadIdx.x;
    __nv_bfloat16 hh, hl;
    if (i < BB * FF) {
        int r = i / FF, cidx = i % FF;
        g_xcur[i] = x[i];
        size_t b = (size_t)r * K1 + cidx;
        split2(x[i], hh, hl);
        g_XSx[b] = hh; g_XSx[b + FF] = hl; g_XSx[b + 2 * FF] = hh;
        __nv_bfloat16 e = __float2bfloat16(eps[i]);   // +-1, exact
        g_epsx[b] = e; g_epsx[b + FF] = __float2bfloat16(0.f); g_epsx[b + 2 * FF] = e;
    }
    if (i < FF * HH) {   // W1 rows 0..127
        int r = i / HH, cidx = i % HH;
        split2(W1[i], hh, hl);
        g_W1x[(size_t)r * HH + cidx] = hh;
        g_W1x[(size_t)(r + FF) * HH + cidx] = hh;
        g_W1x[(size_t)(r + 2 * FF) * HH + cidx] = hl;
    }
    if (i < HH * HH) {
        int r = i / HH, cidx = i % HH;
        split2(W2[i], hh, hl);
        g_W2x[(size_t)r * HH + cidx] = hh;
        g_W2x[(size_t)(r + HH) * HH + cidx] = hh;
        g_W2x[(size_t)(r + 2 * HH) * HH + cidx] = hl;
    }
    if (i < HH * FF) {
        int r = i / FF, cidx = i % FF;
        split2(W3[i], hh, hl);
        g_W3x[(size_t)r * FF + cidx] = hh;
        g_W3x[(size_t)(r + HH) * FF + cidx] = hh;
        g_W3x[(size_t)(r + 2 * HH) * FF + cidx] = hl;
    }
    if (i < BB) g_logdet[i] = 0.f;
}

template <int STAGE>
__global__ void rk_update(float h) {
    int i = blockIdx.x * blockDim.x + threadIdx.x;
    if (i >= BB * FF) return;
    float k = g_K[i];
    float xc = g_xcur[i];
    float xs;
    if (STAGE == 0) {
        g_accX[i] = k;
        xs = xc + 0.5f * h * k;
    } else if (STAGE == 1) {
        g_accX[i] += 2.f * k;
        xs = xc + 0.5f * h * k;
    } else if (STAGE == 2) {
        g_accX[i] += 2.f * k;
        xs = xc + h * k;
    } else {
        float xn = xc + (h / 6.f) * (g_accX[i] + k);
        g_xcur[i] = xn;
        xs = xn;
    }
    {
        int r = i / FF, cidx = i % FF;
        size_t b = (size_t)r * K1 + cidx;
        __nv_bfloat16 hh, hl;
        split2(xs, hh, hl);
        g_XSx[b] = hh; g_XSx[b + FF] = hl; g_XSx[b + 2 * FF] = hh;
    }
    if ((i & (FF - 1)) == 0) {
        int r = i / FF;
        float tr = g_trace[r];
        if (STAGE == 0)      g_accL[r] = tr;
        else if (STAGE == 1) g_accL[r] += 2.f * tr;
        else if (STAGE == 2) g_accL[r] += 2.f * tr;
        else                 g_logdet[r] -= (h / 6.f) * (g_accL[r] + tr);
    }
}

__global__ void finish_k(float* __restrict__ out) {
    int i = blockIdx.x * blockDim.x + threadIdx.x;
    if (i < BB * FF) out[i] = g_xcur[i];
    if (i < BB) out[BB * FF + i] = g_logdet[i];
}

// ---------------- launch ----------------
extern "C" void kernel_launch(void* const* d_in, const int* in_sizes, int n_in,
                              void* d_out, int out_size) {
    const float* x   = (const float*)d_in[0];
    const float* eps = (const float*)d_in[1];
    const float* W1  = (const float*)d_in[2];
    const float* b1  = (const float*)d_in[3];
    const float* W2  = (const float*)d_in[4];
    const float* b2  = (const float*)d_in[5];
    const float* W3  = (const float*)d_in[6];
    const float* b3  = (const float*)d_in[7];
    float* out = (float*)d_out;

    const int ew = (BB * FF + 255) / 256;
    setup_k<<<ew, 256>>>(x, eps, W1, W2, W3);

    // Constant layer-1 tangent pre-activation: T1 = eps @ W1[:128] (exact split)
    gemm_k<E_T1><<<dim3(HH / BN, BB / BM), 256>>>(nullptr, nullptr, 0.f, nullptr);

    const float h = 1.0f / NSTEPS;
    const float stc[4] = {0.f, 0.5f, 0.5f, 1.f};
    const float* w1t = W1 + FF * HH;  // row 128 of W1 (time column)

    for (int s = 0; s < NSTEPS; s++) {
        float t0 = s * h;
        for (int st = 0; st < 4; st++) {
            float tv = t0 + stc[st] * h;
            gemm_k<E_L1> <<<dim3(HH / BN, BB / BM), 256>>>(b1, w1t, tv, nullptr);
            gemm_k<E_L2P><<<dim3(HH / BN, BB / BM), 256>>>(b2, nullptr, 0.f, nullptr);
            gemm_k<E_L2T><<<dim3(HH / BN, BB / BM), 256>>>(nullptr, nullptr, 0.f, nullptr);
            gemm_k<E_L3P><<<dim3(FF / BN, BB / BM), 256>>>(b3, nullptr, 0.f, nullptr);
            gemm_k<E_L3T><<<dim3(FF / BN, BB / BM), 256>>>(nullptr, nullptr, 0.f, eps);
            switch (st) {
                case 0: rk_update<0><<<ew, 256>>>(h); break;
                case 1: rk_update<1><<<ew, 256>>>(h); break;
                case 2: rk_update<2><<<ew, 256>>>(h); break;
                case 3: rk_update<3><<<ew, 256>>>(h); break;
            }
        }
    }
    finish_k<<<ew, 256>>>(out);
}